// round 8
// baseline (speedup 1.0000x reference)
#include <cuda_runtime.h>
#include <cuda_fp16.h>

// Problem constants
#define VSZ   30000
#define OC    128
#define KW    5
#define BATCH 32

constexpr int L    = 2560;          // 40*64 flattened token positions per batch
constexpr int LOUT = L - KW + 1;    // 2556
constexpr int CW   = VSZ * KW;      // 150000 columns (v*5+w)
constexpr int NSUB = 128;           // sub-chunks of the l-range
constexpr int SUBL = 20;            // 128*20 = 2560 >= LOUT

constexpr int NT = (CW + 63) / 64;  // 2344 transpose blocks per half
constexpr int NC = (NSUB / 8) * BATCH; // 512 conv blocks per half (8 warps/block)
constexpr int NB = NT + NC;         // fused grid

// Two half-tables: Kt0 = oc 0..63, Kt1 = oc 64..127, layout [vw][64] halves.
__device__ __align__(16) __half g_Kt0[(size_t)CW * 64];
__device__ __align__(16) __half g_Kt1[(size_t)CW * 64];
// Per-warp partial maxima: [b][sub][oc]
__device__ float g_partial[BATCH][NSUB][OC];

// ---------------------------------------------------------------------------
// Transpose one 64-column tile of one 64-row (oc) half of K into a half-table.
// srcRows = src + rowoff*CW. tile uint[64][33]: bank-conflict-free both sides.
// Write-out: contiguous 128B half-table rows.
// ---------------------------------------------------------------------------
__device__ __forceinline__ void do_transpose(const float* __restrict__ srcRows,
                                             unsigned* __restrict__ dstU, int bx) {
    __shared__ unsigned tile[64][33];
    const int tid    = threadIdx.x;
    const int clocal = tid & 63;
    const int rgrp   = tid >> 6;              // 0..3
    const int cbase  = bx * 64;
    const int c      = cbase + clocal;
    const bool cok   = (c < CW);

    #pragma unroll
    for (int i = 0; i < 8; i++) {
        int rpair = rgrp + i * 4;             // 0..31
        int r = rpair * 2;
        if (cok) {
            float a = __ldcs(srcRows + (size_t) r      * CW + c);
            float b = __ldcs(srcRows + (size_t)(r + 1) * CW + c);
            half2 h = __floats2half2_rn(a, b);   // .x = oc r, .y = oc r+1 (local)
            tile[clocal][rpair] = *reinterpret_cast<unsigned*>(&h);
        }
    }
    __syncthreads();

    const int colu   = tid & 31;              // uint index within half-table row
    const int rowsel = tid >> 5;              // 0..7
    #pragma unroll
    for (int i = 0; i < 8; i++) {
        int row = rowsel + i * 8;             // col-local 0..63
        int vw  = cbase + row;
        if (vw < CW)
            dstU[(size_t)vw * 32 + colu] = tile[row][colu];
    }
}

// ---------------------------------------------------------------------------
// Conv on one oc-half. 8 warps/block, one warp per sub-chunk; each lane owns
// 2 oc (half2), 5 x 128B requests per token. Ids preloaded lane-parallel +
// __shfl. Ring-slot reset MUST be unconditional (boundary flush, see R3).
// ---------------------------------------------------------------------------
__device__ __forceinline__ void addh2(float2& a, unsigned v) {
    float2 f = __half22float2(*reinterpret_cast<half2*>(&v));
    a.x += f.x; a.y += f.y;
}
__device__ __forceinline__ void max2(float2& a, const float2 b) {
    a.x = fmaxf(a.x, b.x); a.y = fmaxf(a.y, b.y);
}

__device__ __forceinline__ void do_conv_half(const unsigned* __restrict__ Kt,
                                             const int* __restrict__ tokens,
                                             int flat, int halfIdx) {
    const int b       = flat >> 4;            // 16 blocks per batch
    const int subBase = (flat & 15) * 8;
    const int warp    = threadIdx.x >> 5;
    const int lane    = threadIdx.x & 31;
    const int sub     = subBase + warp;

    const int l0 = sub * SUBL;
    const int l1 = min(l0 + SUBL, LOUT);
    const int n  = l1 + KW - 1 - l0;          // <= 24

    const int* ids = tokens + b * L;
    int myid = 0;
    if (lane < n) myid = __ldg(ids + l0 + lane);

    float2 acc[5];
    #pragma unroll
    for (int i = 0; i < 5; i++) acc[i] = make_float2(0.f, 0.f);
    float2 vmax = make_float2(0.f, 0.f);      // relu: floor at 0

    #pragma unroll
    for (int j = 0; j < SUBL + KW - 1; j++) {
        if (j < n) {
            int id = __shfl_sync(0xFFFFFFFFu, myid, j);
            // half-table row per id: 5 w-rows x 32 uints (64 halves) = 160 uints
            const unsigned* sp = Kt + (size_t)id * 160 + lane;
            unsigned v0 = __ldg(sp +   0);
            unsigned v1 = __ldg(sp +  32);
            unsigned v2 = __ldg(sp +  64);
            unsigned v3 = __ldg(sp +  96);
            unsigned v4 = __ldg(sp + 128);
            addh2(acc[(j + 5 - 0) % 5], v0);
            addh2(acc[(j + 5 - 1) % 5], v1);
            addh2(acc[(j + 5 - 2) % 5], v2);
            addh2(acc[(j + 5 - 3) % 5], v3);
            addh2(acc[(j + 5 - 4) % 5], v4);
            const int s = (j + 1) % 5;
            if (j >= 4) max2(vmax, acc[s]);
            acc[s] = make_float2(0.f, 0.f);
        }
    }
    float2* dst = reinterpret_cast<float2*>(&g_partial[b][sub][0]);
    dst[halfIdx * 32 + lane] = vmax;
}

// ---------------------------------------------------------------------------
// Kernel T0: transpose oc-half 0 (rows 0..63) -> Kt0
// ---------------------------------------------------------------------------
__global__ void __launch_bounds__(256) transpose0_kernel(const float* __restrict__ src) {
    do_transpose(src, reinterpret_cast<unsigned*>(g_Kt0), blockIdx.x);
}

// ---------------------------------------------------------------------------
// Kernel F (fused): transpose oc-half 1 (rows 64..127) -> Kt1  OVERLAPPED with
// conv-half 0 reading Kt0. Roles interleaved across blockIdx.x by exact linear
// interpolation so conv blocks land in every scheduling wave.
// ---------------------------------------------------------------------------
__global__ void __launch_bounds__(256) fused_kernel(const float* __restrict__ src,
                                                    const int* __restrict__ tokens) {
    const unsigned bid = blockIdx.x;
    const unsigned k0 = (unsigned)(((unsigned long long)bid       * NC) / NB);
    const unsigned k1 = (unsigned)(((unsigned long long)(bid + 1) * NC) / NB);
    if (k1 > k0) {
        do_conv_half(reinterpret_cast<const unsigned*>(g_Kt0), tokens, (int)k0, 0);
    } else {
        do_transpose(src + (size_t)64 * CW, reinterpret_cast<unsigned*>(g_Kt1),
                     (int)(bid - k0));
    }
}

// ---------------------------------------------------------------------------
// Kernel C1: conv-half 1 reading Kt1
// ---------------------------------------------------------------------------
__global__ void __launch_bounds__(256) conv1_kernel(const int* __restrict__ tokens) {
    do_conv_half(reinterpret_cast<const unsigned*>(g_Kt1), tokens, blockIdx.x, 1);
}

// ---------------------------------------------------------------------------
// Kernel 4: reduce sub-chunk maxima + tiny FC.  grid = 32 (b), block = 128.
// ---------------------------------------------------------------------------
__global__ void __launch_bounds__(128) final_kernel(const float* __restrict__ fc1_w,
                                                    const float* __restrict__ fc1_b,
                                                    float* __restrict__ out) {
    const int b  = blockIdx.x;
    const int t  = threadIdx.x;          // = oc
    const int warp = t >> 5, lane = t & 31;

    const float* part = &g_partial[b][0][0]; // [NSUB][128]
    float pooled = 0.f;
    #pragma unroll 8
    for (int s = 0; s < NSUB; s++)
        pooled = fmaxf(pooled, part[s * OC + t]);

    __shared__ float shw[4][4];          // [warp][tc]
    #pragma unroll
    for (int tc = 0; tc < 4; tc++) {
        float v = pooled * fc1_w[tc * OC + t];
        #pragma unroll
        for (int off = 16; off > 0; off >>= 1)
            v += __shfl_down_sync(0xFFFFFFFFu, v, off);
        if (lane == 0) shw[warp][tc] = v;
    }
    __syncthreads();
    if (t < 4) {
        float s = shw[0][t] + shw[1][t] + shw[2][t] + shw[3][t];
        out[b * 4 + t] = s + fc1_b[t];
    }
}

// ---------------------------------------------------------------------------
extern "C" void kernel_launch(void* const* d_in, const int* in_sizes, int n_in,
                              void* d_out, int out_size) {
    const int*   tokens = (const int*)  d_in[0];
    const float* k1     = (const float*)d_in[1];
    const float* fc1w   = (const float*)d_in[2];
    const float* fc1b   = (const float*)d_in[3];
    float*       out    = (float*)d_out;

    transpose0_kernel<<<NT, 256>>>(k1);            // 2344 blocks
    fused_kernel<<<NB, 256>>>(k1, tokens);         // 2856 blocks (T1 + C0)
    conv1_kernel<<<NC, 256>>>(tokens);             // 512 blocks
    final_kernel<<<BATCH, 128>>>(fc1w, fc1b, out);
}

// round 9
// speedup vs baseline: 1.1765x; 1.1765x over previous
#include <cuda_runtime.h>
#include <cuda_fp16.h>

// Problem constants
#define VSZ   30000
#define OC    128
#define KW    5
#define BATCH 32

constexpr int L    = 2560;          // 40*64 flattened token positions per batch
constexpr int LOUT = L - KW + 1;    // 2556
constexpr int CW   = VSZ * KW;      // 150000 columns (v*5+w)
constexpr int NSUB = 128;           // sub-chunks of the l-range
constexpr int SUBL = 20;            // 128*20 = 2560 >= LOUT

// Scratch: transposed fp16 table Kt[v][w][oc]  (38.4 MB, L2-resident)
__device__ __align__(16) __half g_Kt[(size_t)VSZ * KW * OC];
// Per-warp partial maxima: [b][sub][oc]
__device__ float g_partial[BATCH][NSUB][OC];

// ---------------------------------------------------------------------------
// Kernel 1: transpose + fp32->fp16 convert, wide-load version.
// K is (128 x 150000), row = oc, col = v*5+w.  ->  Kt[col][oc] as half.
// Block = 64 columns x 128 oc rows, 256 threads, 4 passes.
// Per pass each thread loads TWO float4 (rows 2RP, 2RP+1 x 4 cols) =
// 32B in flight per thread per pass in 2 LDG.128 (vs 8B in 2 LDG.32 before),
// packs into 4 half2-uints -> tile[col][rowpair]. Write-out: contiguous
// 256B Kt rows, conflict-free smem reads.
// ---------------------------------------------------------------------------
__global__ void __launch_bounds__(256) transpose_kernel(const float* __restrict__ src) {
    __shared__ unsigned tile[64][65];         // [col-local][oc-pair 0..63]
    const int t     = threadIdx.x;
    const int rp0   = t >> 4;                 // 0..15
    const int c4    = (t & 15) * 4;           // column group within tile
    const int cbase = blockIdx.x * 64;
    const int c     = cbase + c4;
    const bool cok  = (c + 3 < CW);           // whole float4 in range (CW%4==0)

    #pragma unroll
    for (int i = 0; i < 4; i++) {
        const int RP = rp0 + 16 * i;          // rowpair 0..63 -> rows 2RP, 2RP+1
        if (cok) {
            const float4 fa = __ldcs(reinterpret_cast<const float4*>(
                                  src + (size_t)(2 * RP)     * CW + c));
            const float4 fb = __ldcs(reinterpret_cast<const float4*>(
                                  src + (size_t)(2 * RP + 1) * CW + c));
            half2 h0 = __floats2half2_rn(fa.x, fb.x);
            half2 h1 = __floats2half2_rn(fa.y, fb.y);
            half2 h2 = __floats2half2_rn(fa.z, fb.z);
            half2 h3 = __floats2half2_rn(fa.w, fb.w);
            tile[c4 + 0][RP] = *reinterpret_cast<unsigned*>(&h0);
            tile[c4 + 1][RP] = *reinterpret_cast<unsigned*>(&h1);
            tile[c4 + 2][RP] = *reinterpret_cast<unsigned*>(&h2);
            tile[c4 + 3][RP] = *reinterpret_cast<unsigned*>(&h3);
        }
    }
    __syncthreads();

    // Write out: 64 Kt rows x 64 uints (128 halfs) each; warp = 128B chunk.
    const int colu   = t & 63;                // uint (rowpair) index in Kt row
    const int rowsel = t >> 6;                // 0..3
    #pragma unroll
    for (int i = 0; i < 16; i++) {
        int row = rowsel + i * 4;             // col-local 0..63
        int vw  = cbase + row;
        if (vw < CW)
            reinterpret_cast<unsigned*>(g_Kt)[(size_t)vw * 64 + colu] = tile[row][colu];
    }
}

// ---------------------------------------------------------------------------
// Kernel 2: gather + sliding-window conv + relu-max  (exact R5 winner).
// grid = (NSUB/8, BATCH), block = 256 (8 warps); ONE warp per sub-chunk.
// Each lane owns 4 consecutive oc as one uint2 (8B) per w -> 5 x 256B L2
// requests per token. Ids preloaded lane-parallel + __shfl.
// Ring-slot reset MUST be unconditional (boundary-pollution flush, see R3).
// ---------------------------------------------------------------------------
__device__ __forceinline__ void addh4(float4& a, const uint2 v) {
    const half2 h0 = *reinterpret_cast<const half2*>(&v.x);
    const half2 h1 = *reinterpret_cast<const half2*>(&v.y);
    float2 f0 = __half22float2(h0);
    float2 f1 = __half22float2(h1);
    a.x += f0.x; a.y += f0.y; a.z += f1.x; a.w += f1.y;
}
__device__ __forceinline__ void max4(float4& a, const float4 b) {
    a.x = fmaxf(a.x, b.x); a.y = fmaxf(a.y, b.y);
    a.z = fmaxf(a.z, b.z); a.w = fmaxf(a.w, b.w);
}

__global__ void __launch_bounds__(256) conv_kernel(const int* __restrict__ tokens) {
    const int b    = blockIdx.y;
    const int warp = threadIdx.x >> 5;
    const int lane = threadIdx.x & 31;
    const int sub  = blockIdx.x * 8 + warp;

    const int l0 = sub * SUBL;
    const int l1 = min(l0 + SUBL, LOUT);
    const int n  = l1 + KW - 1 - l0;     // tokens this sub-chunk (<= 24)

    const int* ids = tokens + b * L;
    int myid = 0;
    if (lane < n) myid = __ldg(ids + l0 + lane);

    const uint2* __restrict__ Kt8 = reinterpret_cast<const uint2*>(g_Kt);

    float4 acc[5];
    #pragma unroll
    for (int i = 0; i < 5; i++) acc[i] = make_float4(0.f, 0.f, 0.f, 0.f);
    float4 vmax = make_float4(0.f, 0.f, 0.f, 0.f);   // relu: floor at 0

    #pragma unroll
    for (int j = 0; j < SUBL + KW - 1; j++) {       // j = p - l0
        if (j < n) {
            int id = __shfl_sync(0xFFFFFFFFu, myid, j);
            // 640 halfs per token row = 160 uint2; w-row = 32 uint2.
            const uint2* srcp = Kt8 + (size_t)id * 160 + lane;
            uint2 v0 = __ldg(srcp +   0);
            uint2 v1 = __ldg(srcp +  32);
            uint2 v2 = __ldg(srcp +  64);
            uint2 v3 = __ldg(srcp +  96);
            uint2 v4 = __ldg(srcp + 128);
            // conv[l = p - w] += K[:, id, w]; slot(l) = (l - l0) mod 5
            addh4(acc[(j + 5 - 0) % 5], v0);
            addh4(acc[(j + 5 - 1) % 5], v1);
            addh4(acc[(j + 5 - 2) % 5], v2);
            addh4(acc[(j + 5 - 3) % 5], v3);
            addh4(acc[(j + 5 - 4) % 5], v4);
            // slot (j+1)%5: completed conv[p-4] when j>=4; stale boundary
            // pollution when j<4 — reset it either way.
            const int s = (j + 1) % 5;
            if (j >= 4) max4(vmax, acc[s]);
            acc[s] = make_float4(0.f, 0.f, 0.f, 0.f);
        }
    }
    float4* dst = reinterpret_cast<float4*>(&g_partial[b][sub][0]);
    dst[lane] = vmax;
}

// ---------------------------------------------------------------------------
// Kernel 3: reduce sub-chunk maxima + tiny FC.  grid = 32 (b), block = 128.
// ---------------------------------------------------------------------------
__global__ void __launch_bounds__(128) final_kernel(const float* __restrict__ fc1_w,
                                                    const float* __restrict__ fc1_b,
                                                    float* __restrict__ out) {
    const int b  = blockIdx.x;
    const int t  = threadIdx.x;          // = oc
    const int warp = t >> 5, lane = t & 31;

    const float* part = &g_partial[b][0][0]; // [NSUB][128]
    float pooled = 0.f;
    #pragma unroll 8
    for (int s = 0; s < NSUB; s++)
        pooled = fmaxf(pooled, part[s * OC + t]);

    __shared__ float shw[4][4];          // [warp][tc]
    #pragma unroll
    for (int tc = 0; tc < 4; tc++) {
        float v = pooled * fc1_w[tc * OC + t];
        #pragma unroll
        for (int off = 16; off > 0; off >>= 1)
            v += __shfl_down_sync(0xFFFFFFFFu, v, off);
        if (lane == 0) shw[warp][tc] = v;
    }
    __syncthreads();
    if (t < 4) {
        float s = shw[0][t] + shw[1][t] + shw[2][t] + shw[3][t];
        out[b * 4 + t] = s + fc1_b[t];
    }
}

// ---------------------------------------------------------------------------
extern "C" void kernel_launch(void* const* d_in, const int* in_sizes, int n_in,
                              void* d_out, int out_size) {
    const int*   tokens = (const int*)  d_in[0];
    const float* k1     = (const float*)d_in[1];
    const float* fc1w   = (const float*)d_in[2];
    const float* fc1b   = (const float*)d_in[3];
    float*       out    = (float*)d_out;

    transpose_kernel<<<(CW + 63) / 64, 256>>>(k1);     // 2344 blocks

    conv_kernel<<<dim3(NSUB / 8, BATCH), 256>>>(tokens);   // (16, 32)

    final_kernel<<<BATCH, 128>>>(fc1w, fc1b, out);
}